// round 9
// baseline (speedup 1.0000x reference)
#include <cuda_runtime.h>
#include <cuda_bf16.h>
#include <math_constants.h>
#include <cstdint>

#define CH    16
#define HID   128
#define IMG   256
#define TILE  16            // 16x16 pixels per tile
#define TOTAL_TILES 8192    // 32 batch * 16 * 16

// ---- smem byte offsets ----
#define OFF_W1   0          // [128n][72k]  bf16 : 128*144  = 18432
#define OFF_W2   18432      // [128n][136k] bf16 : 128*272  = 34816
#define OFF_W3   53248      // [128n][136k] bf16 : 34816
#define OFF_W4   88064      // [16n][136k]  bf16 : 16*272   = 4352
#define OFF_B1   92416      // 128 f32
#define OFF_B2   92928
#define OFF_B3   93440
#define OFF_A1   93952      // layer-1 A: [256m][72k] bf16 : 256*144 = 36864
#define OFF_X0   130816     // halo buf0: 16ch x 18 x 18 fp32 : 20736
#define OFF_X1   151552     // halo buf1: 20736
#define OFF_STG  172288     // x_new staging: 16ch x 256 f32 : 16384
#define SMEM_BYTES 188672

#define SB1 144             // w1 / A1 row stride bytes
#define SB2 272             // w2/w3/w4 row stride bytes

// scratch (device globals: sanctioned alloc-free workaround)
__device__ float         g_xnew[33554432];
__device__ unsigned char g_pre [2097152];

__device__ __forceinline__ uint32_t smem_to_u32(const void* p) {
    uint32_t a;
    asm("{ .reg .u64 t; cvta.to.shared.u64 t, %1; cvt.u32.u64 %0, t; }"
        : "=r"(a) : "l"(p));
    return a;
}
__device__ __forceinline__ uint32_t pack_bf16x2(float lo, float hi) {
    uint32_t r;
    asm("cvt.rn.bf16x2.f32 %0, %1, %2;" : "=r"(r) : "f"(hi), "f"(lo));
    return r;
}
__device__ __forceinline__ float lrelu(float z) {
    return z > 0.0f ? z : 0.01f * z;
}
__device__ __forceinline__ void ldsm4(uint32_t& r0, uint32_t& r1,
                                      uint32_t& r2, uint32_t& r3, uint32_t addr) {
    asm volatile("ldmatrix.sync.aligned.m8n8.x4.shared.b16 {%0,%1,%2,%3}, [%4];"
                 : "=r"(r0), "=r"(r1), "=r"(r2), "=r"(r3) : "r"(addr));
}
__device__ __forceinline__ void mma_bf16(float& c0, float& c1, float& c2, float& c3,
                                         uint32_t a0, uint32_t a1, uint32_t a2, uint32_t a3,
                                         uint32_t b0, uint32_t b1) {
    asm volatile("mma.sync.aligned.m16n8k16.row.col.f32.bf16.bf16.f32 "
                 "{%0,%1,%2,%3}, {%4,%5,%6,%7}, {%8,%9}, {%0,%1,%2,%3};"
                 : "+f"(c0), "+f"(c1), "+f"(c2), "+f"(c3)
                 : "r"(a0), "r"(a1), "r"(a2), "r"(a3), "r"(b0), "r"(b1));
}
__device__ __forceinline__ void cpasync4(uint32_t dst, const void* src, bool ok) {
    uint32_t sz = ok ? 4u : 0u;
    asm volatile("cp.async.ca.shared.global [%0], [%1], 4, %2;"
                 :: "r"(dst), "l"(src), "r"(sz));
}
#define CP_COMMIT() asm volatile("cp.async.commit_group;" ::: "memory")
#define CP_WAIT0()  asm volatile("cp.async.wait_group 0;" ::: "memory")

// async halo prefetch: 16ch x 18x18 fp32, zero-filled OOB, into smem buffer
__device__ __forceinline__ void prefetch_halo(const float* __restrict__ xb,
                                              uint32_t dstbase, int x0, int y0,
                                              int tid) {
    const int c = tid >> 5;
    const int lane = tid & 31;
    const float* srcc = xb + c * (IMG * IMG);
    const uint32_t dstc = dstbase + (uint32_t)c * (324 * 4);
#pragma unroll
    for (int it = 0; it < 11; it++) {
        const int e = lane + it * 32;
        if (it < 10 || e < 324) {
            const int rr = e / 18, cc = e - rr * 18;
            const int gy = y0 + rr - 1, gx = x0 + cc - 1;
            const bool ok = ((unsigned)gy < IMG) && ((unsigned)gx < IMG);
            cpasync4(dstc + (uint32_t)e * 4, srcc + gy * IMG + gx, ok);
        }
    }
}

// GEMM: A (KC k-chunks, regs) x B (smem W[n][k] bf16, padded stride) -> C (NC n-chunks)
template <int KC, int NC>
__device__ __forceinline__ void gemm(const uint32_t (&a)[KC][4], float (&c)[NC][4],
                                     uint32_t wbase, int strideB, int lane) {
    const int nrow = (lane & 7) + ((lane >> 4) << 3);
    const int kofs = ((lane >> 3) & 1) * 16;   // khalf * 8 elems * 2B
#pragma unroll
    for (int kc = 0; kc < KC; kc++) {
#pragma unroll
        for (int p = 0; p < NC / 2; p++) {
            uint32_t addr = wbase + (uint32_t)(p * 16 + nrow) * strideB
                          + (uint32_t)(kc * 32 + kofs);
            uint32_t b0, b1, b2, b3;
            ldsm4(b0, b1, b2, b3, addr);
            mma_bf16(c[2 * p][0], c[2 * p][1], c[2 * p][2], c[2 * p][3],
                     a[kc][0], a[kc][1], a[kc][2], a[kc][3], b0, b1);
            mma_bf16(c[2 * p + 1][0], c[2 * p + 1][1], c[2 * p + 1][2], c[2 * p + 1][3],
                     a[kc][0], a[kc][1], a[kc][2], a[kc][3], b2, b3);
        }
    }
}

// bias + lrelu + repack C(m16n8 x NC) -> A(m16k16 x NC/2) for the next layer
template <int NC>
__device__ __forceinline__ void transition(const float (&c)[NC][4],
                                           uint32_t (&a)[NC / 2][4],
                                           const float* __restrict__ sBias, int lane) {
    const int co = 2 * (lane & 3);
#pragma unroll
    for (int kc = 0; kc < NC / 2; kc++) {
#pragma unroll
        for (int h = 0; h < 2; h++) {
            const int j = 2 * kc + h;
            float2 bp = *reinterpret_cast<const float2*>(sBias + j * 8 + co);
            float v0 = lrelu(c[j][0] + bp.x);
            float v1 = lrelu(c[j][1] + bp.y);
            float v2 = lrelu(c[j][2] + bp.x);
            float v3 = lrelu(c[j][3] + bp.y);
            a[kc][2 * h + 0] = pack_bf16x2(v0, v1);
            a[kc][2 * h + 1] = pack_bf16x2(v2, v3);
        }
    }
}

// stage fp32 weights [N][K] -> smem bf16 padded rows (pad never read)
__device__ __forceinline__ void stage_w(const float* __restrict__ g, char* sw,
                                        int N, int K, int strideB, int tid) {
    for (int i = tid; i < N * K; i += 512) {
        int n = i / K, k = i - n * K;
        *reinterpret_cast<__nv_bfloat16*>(sw + n * strideB + k * 2) =
            __float2bfloat16(g[i]);
    }
}

// =============================== pass 1 ====================================
__global__ void __launch_bounds__(512, 1)
nca_pass1(const float* __restrict__ x,
          const float* __restrict__ w1, const float* __restrict__ b1,
          const float* __restrict__ w2, const float* __restrict__ b2,
          const float* __restrict__ w3, const float* __restrict__ b3,
          const float* __restrict__ w4,
          const float* __restrict__ um) {
    extern __shared__ char smem[];
    const uint32_t smem_base = smem_to_u32(smem);
    const int tid = threadIdx.x;
    const int w = tid >> 5;          // warp id = tile row it owns in MLP
    const int lane = tid & 31;
    float* sStg = reinterpret_cast<float*>(smem + OFF_STG);  // [ch][256]
    const float* sB1 = reinterpret_cast<float*>(smem + OFF_B1);
    const float* sB2 = reinterpret_cast<float*>(smem + OFF_B2);
    const float* sB3 = reinterpret_cast<float*>(smem + OFF_B3);

    // prefetch first tile's halo (overlaps weight staging)
    {
        const int t0 = blockIdx.x;
        const int b0r = t0 >> 8, r0 = t0 & 255;
        prefetch_halo(x + (size_t)b0r * CH * IMG * IMG, smem_base + OFF_X0,
                      (r0 & 15) * TILE, (r0 >> 4) * TILE, tid);
    }
    CP_COMMIT();

    // one-time: stage weights + biases
    stage_w(w1, smem + OFF_W1, 128, 64, SB1, tid);
    stage_w(w2, smem + OFF_W2, 128, 128, SB2, tid);
    stage_w(w3, smem + OFF_W3, 128, 128, SB2, tid);
    stage_w(w4, smem + OFF_W4, 16, 128, SB2, tid);
    if (tid < HID) {
        reinterpret_cast<float*>(smem + OFF_B1)[tid] = b1[tid];
        reinterpret_cast<float*>(smem + OFF_B2)[tid] = b2[tid];
        reinterpret_cast<float*>(smem + OFF_B3)[tid] = b3[tid];
    }

    int buf = 0;
    for (int t = blockIdx.x; t < TOTAL_TILES; t += gridDim.x) {
        const int b = t >> 8;
        const int r = t & 255;
        const int x0 = (r & 15) * TILE, y0 = (r >> 4) * TILE;
        float* sX = reinterpret_cast<float*>(smem + (buf ? OFF_X1 : OFF_X0));

        CP_WAIT0();
        __syncthreads();   // halo[buf] + weights visible; prev iter consumers done

        // issue prefetch of next tile into the other buffer (overlaps everything)
        {
            const int tn = t + gridDim.x;
            if (tn < TOTAL_TILES) {
                const int bn = tn >> 8, rn = tn & 255;
                prefetch_halo(x + (size_t)bn * CH * IMG * IMG,
                              smem_base + (buf ? OFF_X0 : OFF_X1),
                              (rn & 15) * TILE, (rn >> 4) * TILE, tid);
            }
            CP_COMMIT();
        }

        // conv: all 512 threads (2 threads/pixel x 8 channels) -> A1 bf16
        {
            const int pix = tid & 255;
            const int px = pix & 15, py = pix >> 4;
            const int c0 = (tid >> 8) << 3;   // 0 or 8
            char* arow = smem + OFF_A1 + pix * SB1;
#pragma unroll
            for (int ci = 0; ci < 8; ci++) {
                const int c = c0 + ci;
                const float* base = sX + c * 324 + py * 18 + px;
                float v00 = base[0],  v01 = base[1],  v02 = base[2];
                float v10 = base[18], v11 = base[19], v12 = base[20];
                float v20 = base[36], v21 = base[37], v22 = base[38];
                float idn = v11;
                float sx = (v02 + 2.0f * v12 + v22) - (v00 + 2.0f * v10 + v20);
                float sy = (v20 + 2.0f * v21 + v22) - (v00 + 2.0f * v01 + v02);
                float lap = v00 + v01 + v02 + v10 + v12 + v20 + v21 + v22 - 8.0f * v11;
                *reinterpret_cast<uint32_t*>(arow + c * 8)     = pack_bf16x2(idn, sx);
                *reinterpret_cast<uint32_t*>(arow + c * 8 + 4) = pack_bf16x2(sy, lap);
            }
        }
        // pre-alive (tid<256: 3x3 max ch0/1, -inf OOB via clip)
        if (tid < 256) {
            const int px = tid & 15, py = tid >> 4;
            float mx0 = -CUDART_INF_F, mx1 = -CUDART_INF_F;
#pragma unroll
            for (int dr = 0; dr < 3; dr++)
#pragma unroll
                for (int dc = 0; dc < 3; dc++) {
                    int gy = y0 + py + dr - 1, gx = x0 + px + dc - 1;
                    if (gy >= 0 && gy < IMG && gx >= 0 && gx < IMG) {
                        mx0 = fmaxf(mx0, sX[0 * 324 + (py + dr) * 18 + (px + dc)]);
                        mx1 = fmaxf(mx1, sX[1 * 324 + (py + dr) * 18 + (px + dc)]);
                    }
                }
            float s = fabsf(mx0) + fabsf(mx1);
            g_pre[b * (IMG * IMG) + (y0 + py) * IMG + (x0 + px)] = (s > 0.01f) ? 1 : 0;
        }
        __syncthreads();

        // ---- per-warp register-resident MLP chain (warp owns rows m=16w..16w+15)
        {
            uint32_t a1[4][4];
            {
                const uint32_t abase = smem_base + OFF_A1
                    + (uint32_t)(16 * w + (lane & 15)) * SB1 + (uint32_t)(lane >> 4) * 16;
#pragma unroll
                for (int kc = 0; kc < 4; kc++)
                    ldsm4(a1[kc][0], a1[kc][1], a1[kc][2], a1[kc][3], abase + kc * 32);
            }
            float c[16][4];
#pragma unroll
            for (int j = 0; j < 16; j++) { c[j][0] = c[j][1] = c[j][2] = c[j][3] = 0.f; }
            gemm<4, 16>(a1, c, smem_base + OFF_W1, SB1, lane);

            uint32_t a2[8][4];
            transition<16>(c, a2, sB1, lane);
#pragma unroll
            for (int j = 0; j < 16; j++) { c[j][0] = c[j][1] = c[j][2] = c[j][3] = 0.f; }
            gemm<8, 16>(a2, c, smem_base + OFF_W2, SB2, lane);

            uint32_t a3[8][4];
            transition<16>(c, a3, sB2, lane);
#pragma unroll
            for (int j = 0; j < 16; j++) { c[j][0] = c[j][1] = c[j][2] = c[j][3] = 0.f; }
            gemm<8, 16>(a3, c, smem_base + OFF_W3, SB2, lane);

            uint32_t a4[8][4];
            transition<16>(c, a4, sB3, lane);
            float c4[2][4];
#pragma unroll
            for (int j = 0; j < 2; j++) { c4[j][0] = c4[j][1] = c4[j][2] = c4[j][3] = 0.f; }
            gemm<8, 2>(a4, c4, smem_base + OFF_W4, SB2, lane);

            // residual update -> staging (x fp32 from halo, dy bf16-derived)
            const int pxl = lane >> 2, pxh = pxl + 8;
            const int ch0 = 2 * (lane & 3);
            const float uml = um[b * (IMG * IMG) + (y0 + w) * IMG + x0 + pxl];
            const float umh = um[b * (IMG * IMG) + (y0 + w) * IMG + x0 + pxh];
#pragma unroll
            for (int j = 0; j < 2; j++) {
                const int cA = 8 * j + ch0, cB = cA + 1;
                const float xAl = sX[cA * 324 + (w + 1) * 18 + (pxl + 1)];
                const float xBl = sX[cB * 324 + (w + 1) * 18 + (pxl + 1)];
                const float xAh = sX[cA * 324 + (w + 1) * 18 + (pxh + 1)];
                const float xBh = sX[cB * 324 + (w + 1) * 18 + (pxh + 1)];
                sStg[cA * 256 + w * 16 + pxl] = xAl + c4[j][0] * uml;
                sStg[cB * 256 + w * 16 + pxl] = xBl + c4[j][1] * uml;
                sStg[cA * 256 + w * 16 + pxh] = xAh + c4[j][2] * umh;
                sStg[cB * 256 + w * 16 + pxh] = xBh + c4[j][3] * umh;
            }
        }
        __syncthreads();

        // coalesced write-out: thread -> (ch, y, half-row of 8 px)
        {
            const int ch = tid >> 5, rest = tid & 31;
            const int yy = rest >> 1, half = rest & 1;
            const float* src = sStg + ch * 256 + yy * 16 + half * 8;
            float* dst = g_xnew + (size_t)b * CH * IMG * IMG
                       + (size_t)ch * IMG * IMG + (size_t)(y0 + yy) * IMG + x0 + half * 8;
            float4 v0 = *reinterpret_cast<const float4*>(src);
            float4 v1 = *reinterpret_cast<const float4*>(src + 4);
            *reinterpret_cast<float4*>(dst)     = v0;
            *reinterpret_cast<float4*>(dst + 4) = v1;
        }
        buf ^= 1;
    }
}

// =============================== pass 2 ====================================
__global__ void __launch_bounds__(256, 4)
nca_pass2(float* __restrict__ out) {
    __shared__ float s0[10][36];
    __shared__ float s1[10][36];
    const int tid = threadIdx.x;
    const int bx = blockIdx.x, by = blockIdx.y, b = blockIdx.z;
    const int x0 = bx * 32, y0 = by * 8;
    const float* xb = g_xnew + (size_t)b * CH * IMG * IMG;

    for (int i = tid; i < 10 * 34; i += 256) {
        int r = i / 34, col = i % 34;
        int gy = y0 + r - 1, gx = x0 + col - 1;
        float v0 = -CUDART_INF_F, v1 = -CUDART_INF_F;
        if (gy >= 0 && gy < IMG && gx >= 0 && gx < IMG) {
            v0 = xb[gy * IMG + gx];
            v1 = xb[IMG * IMG + gy * IMG + gx];
        }
        s0[r][col] = v0;
        s1[r][col] = v1;
    }
    __syncthreads();

    int px = tid & 31, py = tid >> 5;
    float mx0 = -CUDART_INF_F, mx1 = -CUDART_INF_F;
#pragma unroll
    for (int dr = 0; dr < 3; dr++)
#pragma unroll
        for (int dc = 0; dc < 3; dc++) {
            mx0 = fmaxf(mx0, s0[py + dr][px + dc]);
            mx1 = fmaxf(mx1, s1[py + dr][px + dc]);
        }
    float s = fabsf(mx0) + fabsf(mx1);
    int gy = y0 + py, gx = x0 + px;
    bool post = (s > 0.01f);
    bool pre = g_pre[b * (IMG * IMG) + gy * IMG + gx] != 0;
    float alive = (pre && post) ? 1.0f : 0.0f;

    size_t base = (size_t)b * CH * IMG * IMG + (size_t)gy * IMG + gx;
#pragma unroll
    for (int c = 0; c < CH; c++)
        out[base + (size_t)c * IMG * IMG] =
            g_xnew[base + (size_t)c * IMG * IMG] * alive;
}

extern "C" void kernel_launch(void* const* d_in, const int* in_sizes, int n_in,
                              void* d_out, int out_size) {
    const float* x  = (const float*)d_in[0];
    const float* w1 = (const float*)d_in[1];
    const float* b1 = (const float*)d_in[2];
    const float* w2 = (const float*)d_in[3];
    const float* b2 = (const float*)d_in[4];
    const float* w3 = (const float*)d_in[5];
    const float* b3 = (const float*)d_in[6];
    const float* w4 = (const float*)d_in[7];
    const float* um = (const float*)d_in[8];

    cudaFuncSetAttribute(nca_pass1, cudaFuncAttributeMaxDynamicSharedMemorySize,
                         SMEM_BYTES);
    nca_pass1<<<148, 512, SMEM_BYTES>>>(x, w1, b1, w2, b2, w3, b3, w4, um);

    dim3 g2(IMG / 32, IMG / 8, 32);
    nca_pass2<<<g2, 256>>>((float*)d_out);
}

// round 12
// speedup vs baseline: 1.4635x; 1.4635x over previous
#include <cuda_runtime.h>
#include <cuda_bf16.h>
#include <math_constants.h>
#include <cstdint>

#define CH    16
#define HID   128
#define IMG   256
#define TILE  16            // 16x16 pixels per tile
#define TOTAL_TILES 8192    // 32 batch * 16 * 16

// ---- smem byte offsets ----
#define OFF_W1   0          // [128n][72k]  bf16 : 128*144  = 18432
#define OFF_W2   18432      // [128n][136k] bf16 : 128*272  = 34816
#define OFF_W3   53248      // [128n][136k] bf16 : 34816
#define OFF_W4   88064      // [16n][136k]  bf16 : 16*272   = 4352
#define OFF_B1   92416      // 128 f32
#define OFF_B2   92928
#define OFF_B3   93440
#define OFF_A1   93952      // layer-1 A: [256m][72k] bf16 : 256*144 = 36864
#define OFF_X    130816     // halo: 16ch x 18 x 18 fp32 : 20736
#define OFF_STG  151552     // x_new staging: 16ch x 256 f32 : 16384
#define SMEM_BYTES 167936

#define SB1 144             // w1 / A1 row stride bytes
#define SB2 272             // w2/w3/w4 row stride bytes

// scratch (device globals: sanctioned alloc-free workaround)
__device__ float         g_xnew[33554432];
__device__ unsigned char g_pre [2097152];

__device__ __forceinline__ uint32_t smem_to_u32(const void* p) {
    uint32_t a;
    asm("{ .reg .u64 t; cvta.to.shared.u64 t, %1; cvt.u32.u64 %0, t; }"
        : "=r"(a) : "l"(p));
    return a;
}
__device__ __forceinline__ uint32_t pack_bf16x2(float lo, float hi) {
    uint32_t r;
    asm("cvt.rn.bf16x2.f32 %0, %1, %2;" : "=r"(r) : "f"(hi), "f"(lo));
    return r;
}
__device__ __forceinline__ float lrelu(float z) {
    return z > 0.0f ? z : 0.01f * z;
}
__device__ __forceinline__ void ldsm4(uint32_t& r0, uint32_t& r1,
                                      uint32_t& r2, uint32_t& r3, uint32_t addr) {
    asm volatile("ldmatrix.sync.aligned.m8n8.x4.shared.b16 {%0,%1,%2,%3}, [%4];"
                 : "=r"(r0), "=r"(r1), "=r"(r2), "=r"(r3) : "r"(addr));
}
__device__ __forceinline__ void mma_bf16(float& c0, float& c1, float& c2, float& c3,
                                         uint32_t a0, uint32_t a1, uint32_t a2, uint32_t a3,
                                         uint32_t b0, uint32_t b1) {
    asm volatile("mma.sync.aligned.m16n8k16.row.col.f32.bf16.bf16.f32 "
                 "{%0,%1,%2,%3}, {%4,%5,%6,%7}, {%8,%9}, {%0,%1,%2,%3};"
                 : "+f"(c0), "+f"(c1), "+f"(c2), "+f"(c3)
                 : "r"(a0), "r"(a1), "r"(a2), "r"(a3), "r"(b0), "r"(b1));
}

// halo in registers: warp = channel (tid>>5), lane covers 324 elems in 11 strides
__device__ __forceinline__ void halo_ld(float (&h)[11], const float* __restrict__ srcc,
                                        int x0, int y0, int lane) {
#pragma unroll
    for (int it = 0; it < 11; it++) {
        const int e = lane + it * 32;
        h[it] = 0.0f;
        if (it < 10 || e < 324) {
            const int rr = e / 18, cc = e - rr * 18;
            const int gy = y0 + rr - 1, gx = x0 + cc - 1;
            if (((unsigned)gy < IMG) && ((unsigned)gx < IMG))
                h[it] = __ldg(srcc + gy * IMG + gx);
        }
    }
}
__device__ __forceinline__ void halo_st(const float (&h)[11], float* sXc, int lane) {
#pragma unroll
    for (int it = 0; it < 11; it++) {
        const int e = lane + it * 32;
        if (it < 10 || e < 324) sXc[e] = h[it];
    }
}

// GEMM: A (KC k-chunks, regs) x B (smem W[n][k] bf16, padded stride) -> C (NC n-chunks)
template <int KC, int NC>
__device__ __forceinline__ void gemm(const uint32_t (&a)[KC][4], float (&c)[NC][4],
                                     uint32_t wbase, int strideB, int lane) {
    const int nrow = (lane & 7) + ((lane >> 4) << 3);
    const int kofs = ((lane >> 3) & 1) * 16;   // khalf * 8 elems * 2B
#pragma unroll
    for (int kc = 0; kc < KC; kc++) {
#pragma unroll
        for (int p = 0; p < NC / 2; p++) {
            uint32_t addr = wbase + (uint32_t)(p * 16 + nrow) * strideB
                          + (uint32_t)(kc * 32 + kofs);
            uint32_t b0, b1, b2, b3;
            ldsm4(b0, b1, b2, b3, addr);
            mma_bf16(c[2 * p][0], c[2 * p][1], c[2 * p][2], c[2 * p][3],
                     a[kc][0], a[kc][1], a[kc][2], a[kc][3], b0, b1);
            mma_bf16(c[2 * p + 1][0], c[2 * p + 1][1], c[2 * p + 1][2], c[2 * p + 1][3],
                     a[kc][0], a[kc][1], a[kc][2], a[kc][3], b2, b3);
        }
    }
}

// bias + lrelu + repack C(m16n8 x NC) -> A(m16k16 x NC/2) for the next layer
template <int NC>
__device__ __forceinline__ void transition(const float (&c)[NC][4],
                                           uint32_t (&a)[NC / 2][4],
                                           const float* __restrict__ sBias, int lane) {
    const int co = 2 * (lane & 3);
#pragma unroll
    for (int kc = 0; kc < NC / 2; kc++) {
#pragma unroll
        for (int h = 0; h < 2; h++) {
            const int j = 2 * kc + h;
            float2 bp = *reinterpret_cast<const float2*>(sBias + j * 8 + co);
            float v0 = lrelu(c[j][0] + bp.x);
            float v1 = lrelu(c[j][1] + bp.y);
            float v2 = lrelu(c[j][2] + bp.x);
            float v3 = lrelu(c[j][3] + bp.y);
            a[kc][2 * h + 0] = pack_bf16x2(v0, v1);
            a[kc][2 * h + 1] = pack_bf16x2(v2, v3);
        }
    }
}

// stage fp32 weights [N][K] -> smem bf16 padded rows (pad never read)
__device__ __forceinline__ void stage_w(const float* __restrict__ g, char* sw,
                                        int N, int K, int strideB, int tid) {
    for (int i = tid; i < N * K; i += 512) {
        int n = i / K, k = i - n * K;
        *reinterpret_cast<__nv_bfloat16*>(sw + n * strideB + k * 2) =
            __float2bfloat16(g[i]);
    }
}

// =============================== pass 1 ====================================
__global__ void __launch_bounds__(512, 1)
nca_pass1(const float* __restrict__ x,
          const float* __restrict__ w1, const float* __restrict__ b1,
          const float* __restrict__ w2, const float* __restrict__ b2,
          const float* __restrict__ w3, const float* __restrict__ b3,
          const float* __restrict__ w4,
          const float* __restrict__ um) {
    extern __shared__ char smem[];
    const uint32_t smem_base = smem_to_u32(smem);
    const int tid = threadIdx.x;
    const int w = tid >> 5;          // warp id; also = halo channel it loads
    const int lane = tid & 31;
    float* sX   = reinterpret_cast<float*>(smem + OFF_X);    // [ch][324]
    float* sStg = reinterpret_cast<float*>(smem + OFF_STG);  // [ch][256]
    const float* sB1 = reinterpret_cast<float*>(smem + OFF_B1);
    const float* sB2 = reinterpret_cast<float*>(smem + OFF_B2);
    const float* sB3 = reinterpret_cast<float*>(smem + OFF_B3);

    // preload first tile's halo into registers (overlaps weight staging LDGs)
    float hreg[11];
    {
        const int t0 = blockIdx.x;
        const int b0r = t0 >> 8, r0 = t0 & 255;
        halo_ld(hreg, x + (size_t)b0r * CH * IMG * IMG + (size_t)w * IMG * IMG,
                (r0 & 15) * TILE, (r0 >> 4) * TILE, lane);
    }

    // one-time: stage weights + biases
    stage_w(w1, smem + OFF_W1, 128, 64, SB1, tid);
    stage_w(w2, smem + OFF_W2, 128, 128, SB2, tid);
    stage_w(w3, smem + OFF_W3, 128, 128, SB2, tid);
    stage_w(w4, smem + OFF_W4, 16, 128, SB2, tid);
    if (tid < HID) {
        reinterpret_cast<float*>(smem + OFF_B1)[tid] = b1[tid];
        reinterpret_cast<float*>(smem + OFF_B2)[tid] = b2[tid];
        reinterpret_cast<float*>(smem + OFF_B3)[tid] = b3[tid];
    }

    for (int t = blockIdx.x; t < TOTAL_TILES; t += gridDim.x) {
        const int b = t >> 8;
        const int r = t & 255;
        const int x0 = (r & 15) * TILE, y0 = (r >> 4) * TILE;

        // store prefetched halo regs -> sX (safe: prior iter's sX readers are
        // all before its pre-writeout barrier; writeout touches only sStg)
        halo_st(hreg, sX + w * 324, lane);
        __syncthreads();

        // conv: all 512 threads (2 threads/pixel x 8 channels) -> A1 bf16
        {
            const int pix = tid & 255;
            const int px = pix & 15, py = pix >> 4;
            const int c0 = (tid >> 8) << 3;   // 0 or 8
            char* arow = smem + OFF_A1 + pix * SB1;
#pragma unroll
            for (int ci = 0; ci < 8; ci++) {
                const int c = c0 + ci;
                const float* base = sX + c * 324 + py * 18 + px;
                float v00 = base[0],  v01 = base[1],  v02 = base[2];
                float v10 = base[18], v11 = base[19], v12 = base[20];
                float v20 = base[36], v21 = base[37], v22 = base[38];
                float idn = v11;
                float sx = (v02 + 2.0f * v12 + v22) - (v00 + 2.0f * v10 + v20);
                float sy = (v20 + 2.0f * v21 + v22) - (v00 + 2.0f * v01 + v02);
                float lap = v00 + v01 + v02 + v10 + v12 + v20 + v21 + v22 - 8.0f * v11;
                *reinterpret_cast<uint32_t*>(arow + c * 8)     = pack_bf16x2(idn, sx);
                *reinterpret_cast<uint32_t*>(arow + c * 8 + 4) = pack_bf16x2(sy, lap);
            }
        }
        // pre-alive (tid<256: 3x3 max ch0/1, -inf OOB via clip)
        if (tid < 256) {
            const int px = tid & 15, py = tid >> 4;
            float mx0 = -CUDART_INF_F, mx1 = -CUDART_INF_F;
#pragma unroll
            for (int dr = 0; dr < 3; dr++)
#pragma unroll
                for (int dc = 0; dc < 3; dc++) {
                    int gy = y0 + py + dr - 1, gx = x0 + px + dc - 1;
                    if (gy >= 0 && gy < IMG && gx >= 0 && gx < IMG) {
                        mx0 = fmaxf(mx0, sX[0 * 324 + (py + dr) * 18 + (px + dc)]);
                        mx1 = fmaxf(mx1, sX[1 * 324 + (py + dr) * 18 + (px + dc)]);
                    }
                }
            float s = fabsf(mx0) + fabsf(mx1);
            g_pre[b * (IMG * IMG) + (y0 + py) * IMG + (x0 + px)] = (s > 0.01f) ? 1 : 0;
        }
        __syncthreads();

        // prefetch next tile's halo into registers (LDG latency hidden by MLP)
        {
            const int tn = t + gridDim.x;
            if (tn < TOTAL_TILES) {
                const int bn = tn >> 8, rn = tn & 255;
                halo_ld(hreg, x + (size_t)bn * CH * IMG * IMG + (size_t)w * IMG * IMG,
                        ((rn & 15)) * TILE, ((rn >> 4)) * TILE, lane);
            }
        }

        // ---- per-warp register-resident MLP chain (warp owns rows m=16w..16w+15)
        {
            uint32_t a1[4][4];
            {
                const uint32_t abase = smem_base + OFF_A1
                    + (uint32_t)(16 * w + (lane & 15)) * SB1 + (uint32_t)(lane >> 4) * 16;
#pragma unroll
                for (int kc = 0; kc < 4; kc++)
                    ldsm4(a1[kc][0], a1[kc][1], a1[kc][2], a1[kc][3], abase + kc * 32);
            }
            float c[16][4];
#pragma unroll
            for (int j = 0; j < 16; j++) { c[j][0] = c[j][1] = c[j][2] = c[j][3] = 0.f; }
            gemm<4, 16>(a1, c, smem_base + OFF_W1, SB1, lane);

            uint32_t a2[8][4];
            transition<16>(c, a2, sB1, lane);
#pragma unroll
            for (int j = 0; j < 16; j++) { c[j][0] = c[j][1] = c[j][2] = c[j][3] = 0.f; }
            gemm<8, 16>(a2, c, smem_base + OFF_W2, SB2, lane);

            uint32_t a3[8][4];
            transition<16>(c, a3, sB2, lane);
#pragma unroll
            for (int j = 0; j < 16; j++) { c[j][0] = c[j][1] = c[j][2] = c[j][3] = 0.f; }
            gemm<8, 16>(a3, c, smem_base + OFF_W3, SB2, lane);

            uint32_t a4[8][4];
            transition<16>(c, a4, sB3, lane);
            float c4[2][4];
#pragma unroll
            for (int j = 0; j < 2; j++) { c4[j][0] = c4[j][1] = c4[j][2] = c4[j][3] = 0.f; }
            gemm<8, 2>(a4, c4, smem_base + OFF_W4, SB2, lane);

            // residual update -> staging (x fp32 from halo, dy bf16-derived)
            const int pxl = lane >> 2, pxh = pxl + 8;
            const int ch0 = 2 * (lane & 3);
            const float uml = um[b * (IMG * IMG) + (y0 + w) * IMG + x0 + pxl];
            const float umh = um[b * (IMG * IMG) + (y0 + w) * IMG + x0 + pxh];
#pragma unroll
            for (int j = 0; j < 2; j++) {
                const int cA = 8 * j + ch0, cB = cA + 1;
                const float xAl = sX[cA * 324 + (w + 1) * 18 + (pxl + 1)];
                const float xBl = sX[cB * 324 + (w + 1) * 18 + (pxl + 1)];
                const float xAh = sX[cA * 324 + (w + 1) * 18 + (pxh + 1)];
                const float xBh = sX[cB * 324 + (w + 1) * 18 + (pxh + 1)];
                sStg[cA * 256 + w * 16 + pxl] = xAl + c4[j][0] * uml;
                sStg[cB * 256 + w * 16 + pxl] = xBl + c4[j][1] * uml;
                sStg[cA * 256 + w * 16 + pxh] = xAh + c4[j][2] * umh;
                sStg[cB * 256 + w * 16 + pxh] = xBh + c4[j][3] * umh;
            }
        }
        __syncthreads();

        // coalesced write-out: thread -> (ch, y, half-row of 8 px)
        {
            const int ch = tid >> 5, rest = tid & 31;
            const int yy = rest >> 1, half = rest & 1;
            const float* src = sStg + ch * 256 + yy * 16 + half * 8;
            float* dst = g_xnew + (size_t)b * CH * IMG * IMG
                       + (size_t)ch * IMG * IMG + (size_t)(y0 + yy) * IMG + x0 + half * 8;
            float4 v0 = *reinterpret_cast<const float4*>(src);
            float4 v1 = *reinterpret_cast<const float4*>(src + 4);
            *reinterpret_cast<float4*>(dst)     = v0;
            *reinterpret_cast<float4*>(dst + 4) = v1;
        }
    }
}

// =============================== pass 2 ====================================
__global__ void __launch_bounds__(256, 4)
nca_pass2(float* __restrict__ out) {
    __shared__ float s0[10][36];
    __shared__ float s1[10][36];
    const int tid = threadIdx.x;
    const int bx = blockIdx.x, by = blockIdx.y, b = blockIdx.z;
    const int x0 = bx * 32, y0 = by * 8;
    const float* xb = g_xnew + (size_t)b * CH * IMG * IMG;

    for (int i = tid; i < 10 * 34; i += 256) {
        int r = i / 34, col = i % 34;
        int gy = y0 + r - 1, gx = x0 + col - 1;
        float v0 = -CUDART_INF_F, v1 = -CUDART_INF_F;
        if (gy >= 0 && gy < IMG && gx >= 0 && gx < IMG) {
            v0 = xb[gy * IMG + gx];
            v1 = xb[IMG * IMG + gy * IMG + gx];
        }
        s0[r][col] = v0;
        s1[r][col] = v1;
    }
    __syncthreads();

    int px = tid & 31, py = tid >> 5;
    float mx0 = -CUDART_INF_F, mx1 = -CUDART_INF_F;
#pragma unroll
    for (int dr = 0; dr < 3; dr++)
#pragma unroll
        for (int dc = 0; dc < 3; dc++) {
            mx0 = fmaxf(mx0, s0[py + dr][px + dc]);
            mx1 = fmaxf(mx1, s1[py + dr][px + dc]);
        }
    float s = fabsf(mx0) + fabsf(mx1);
    int gy = y0 + py, gx = x0 + px;
    bool post = (s > 0.01f);
    bool pre = g_pre[b * (IMG * IMG) + gy * IMG + gx] != 0;
    float alive = (pre && post) ? 1.0f : 0.0f;

    size_t base = (size_t)b * CH * IMG * IMG + (size_t)gy * IMG + gx;
#pragma unroll
    for (int c = 0; c < CH; c++)
        out[base + (size_t)c * IMG * IMG] =
            g_xnew[base + (size_t)c * IMG * IMG] * alive;
}

extern "C" void kernel_launch(void* const* d_in, const int* in_sizes, int n_in,
                              void* d_out, int out_size) {
    const float* x  = (const float*)d_in[0];
    const float* w1 = (const float*)d_in[1];
    const float* b1 = (const float*)d_in[2];
    const float* w2 = (const float*)d_in[3];
    const float* b2 = (const float*)d_in[4];
    const float* w3 = (const float*)d_in[5];
    const float* b3 = (const float*)d_in[6];
    const float* w4 = (const float*)d_in[7];
    const float* um = (const float*)d_in[8];

    cudaFuncSetAttribute(nca_pass1, cudaFuncAttributeMaxDynamicSharedMemorySize,
                         SMEM_BYTES);
    nca_pass1<<<148, 512, SMEM_BYTES>>>(x, w1, b1, w2, b2, w3, b3, w4, um);

    dim3 g2(IMG / 32, IMG / 8, 32);
    nca_pass2<<<g2, 256>>>((float*)d_out);
}

// round 15
// speedup vs baseline: 1.4688x; 1.0036x over previous
#include <cuda_runtime.h>
#include <cuda_bf16.h>
#include <math_constants.h>
#include <cstdint>

#define CH    16
#define HID   128
#define IMG   256
#define TILE  16            // 16x16 pixels per tile
#define TOTAL_TILES 8192    // 32 batch * 16 * 16

// ---- smem byte offsets ----
#define OFF_W1   0          // [128n][72k]  bf16 : 128*144  = 18432
#define OFF_W2   18432      // [128n][136k] bf16 : 128*272  = 34816
#define OFF_W3   53248      // [128n][136k] bf16 : 34816
#define OFF_W4   88064      // [16n][136k]  bf16 : 16*272   = 4352
#define OFF_B1   92416      // 128 f32
#define OFF_B2   92928
#define OFF_B3   93440
#define OFF_A1   93952      // layer-1 A: [256m][72k] bf16 : 256*144 = 36864
#define OFF_X    130816     // halo: 16ch x 18 x 18 fp32 : 20736
#define OFF_STG  151552     // x_new staging: 16ch x 256 f32 : 16384
#define SMEM_BYTES 167936

#define SB1 144             // w1 / A1 row stride bytes
#define SB2 272             // w2/w3/w4 row stride bytes

// scratch (device globals: sanctioned alloc-free workaround)
__device__ float         g_xnew[33554432];
__device__ unsigned char g_pre [2097152];

__device__ __forceinline__ uint32_t smem_to_u32(const void* p) {
    uint32_t a;
    asm("{ .reg .u64 t; cvta.to.shared.u64 t, %1; cvt.u32.u64 %0, t; }"
        : "=r"(a) : "l"(p));
    return a;
}
__device__ __forceinline__ uint32_t pack_bf16x2(float lo, float hi) {
    uint32_t r;
    asm("cvt.rn.bf16x2.f32 %0, %1, %2;" : "=r"(r) : "f"(hi), "f"(lo));
    return r;
}
__device__ __forceinline__ float lrelu(float z) {
    return z > 0.0f ? z : 0.01f * z;
}
__device__ __forceinline__ void ldsm4(uint32_t& r0, uint32_t& r1,
                                      uint32_t& r2, uint32_t& r3, uint32_t addr) {
    asm volatile("ldmatrix.sync.aligned.m8n8.x4.shared.b16 {%0,%1,%2,%3}, [%4];"
                 : "=r"(r0), "=r"(r1), "=r"(r2), "=r"(r3) : "r"(addr));
}
__device__ __forceinline__ void mma_bf16(float& c0, float& c1, float& c2, float& c3,
                                         uint32_t a0, uint32_t a1, uint32_t a2, uint32_t a3,
                                         uint32_t b0, uint32_t b1) {
    asm volatile("mma.sync.aligned.m16n8k16.row.col.f32.bf16.bf16.f32 "
                 "{%0,%1,%2,%3}, {%4,%5,%6,%7}, {%8,%9}, {%0,%1,%2,%3};"
                 : "+f"(c0), "+f"(c1), "+f"(c2), "+f"(c3)
                 : "r"(a0), "r"(a1), "r"(a2), "r"(a3), "r"(b0), "r"(b1));
}

// halo in registers: warp = channel (tid>>5), lane covers 324 elems in 11 strides
__device__ __forceinline__ void halo_ld(float (&h)[11], const float* __restrict__ srcc,
                                        int x0, int y0, int lane) {
#pragma unroll
    for (int it = 0; it < 11; it++) {
        const int e = lane + it * 32;
        h[it] = 0.0f;
        if (it < 10 || e < 324) {
            const int rr = e / 18, cc = e - rr * 18;
            const int gy = y0 + rr - 1, gx = x0 + cc - 1;
            if (((unsigned)gy < IMG) && ((unsigned)gx < IMG))
                h[it] = __ldg(srcc + gy * IMG + gx);
        }
    }
}
__device__ __forceinline__ void halo_st(const float (&h)[11], float* sXc, int lane) {
#pragma unroll
    for (int it = 0; it < 11; it++) {
        const int e = lane + it * 32;
        if (it < 10 || e < 324) sXc[e] = h[it];
    }
}

// GEMM: A (KC k-chunks, regs) x B (smem W[n][k] bf16, padded stride) -> C (NC n-chunks)
template <int KC, int NC>
__device__ __forceinline__ void gemm(const uint32_t (&a)[KC][4], float (&c)[NC][4],
                                     uint32_t wbase, int strideB, int lane) {
    const int nrow = (lane & 7) + ((lane >> 4) << 3);
    const int kofs = ((lane >> 3) & 1) * 16;   // khalf * 8 elems * 2B
#pragma unroll
    for (int kc = 0; kc < KC; kc++) {
#pragma unroll
        for (int p = 0; p < NC / 2; p++) {
            uint32_t addr = wbase + (uint32_t)(p * 16 + nrow) * strideB
                          + (uint32_t)(kc * 32 + kofs);
            uint32_t b0, b1, b2, b3;
            ldsm4(b0, b1, b2, b3, addr);
            mma_bf16(c[2 * p][0], c[2 * p][1], c[2 * p][2], c[2 * p][3],
                     a[kc][0], a[kc][1], a[kc][2], a[kc][3], b0, b1);
            mma_bf16(c[2 * p + 1][0], c[2 * p + 1][1], c[2 * p + 1][2], c[2 * p + 1][3],
                     a[kc][0], a[kc][1], a[kc][2], a[kc][3], b2, b3);
        }
    }
}

// bias + lrelu + repack C(m16n8 x NC) -> A(m16k16 x NC/2) for the next layer
template <int NC>
__device__ __forceinline__ void transition(const float (&c)[NC][4],
                                           uint32_t (&a)[NC / 2][4],
                                           const float* __restrict__ sBias, int lane) {
    const int co = 2 * (lane & 3);
#pragma unroll
    for (int kc = 0; kc < NC / 2; kc++) {
#pragma unroll
        for (int h = 0; h < 2; h++) {
            const int j = 2 * kc + h;
            float2 bp = *reinterpret_cast<const float2*>(sBias + j * 8 + co);
            float v0 = lrelu(c[j][0] + bp.x);
            float v1 = lrelu(c[j][1] + bp.y);
            float v2 = lrelu(c[j][2] + bp.x);
            float v3 = lrelu(c[j][3] + bp.y);
            a[kc][2 * h + 0] = pack_bf16x2(v0, v1);
            a[kc][2 * h + 1] = pack_bf16x2(v2, v3);
        }
    }
}

// stage fp32 weights [N][K] -> smem bf16 padded rows (pad never read)
__device__ __forceinline__ void stage_w(const float* __restrict__ g, char* sw,
                                        int N, int K, int strideB, int tid) {
    for (int i = tid; i < N * K; i += 512) {
        int n = i / K, k = i - n * K;
        *reinterpret_cast<__nv_bfloat16*>(sw + n * strideB + k * 2) =
            __float2bfloat16(g[i]);
    }
}

// =============================== pass 1 ====================================
__global__ void __launch_bounds__(512, 1)
nca_pass1(const float* __restrict__ x,
          const float* __restrict__ w1, const float* __restrict__ b1,
          const float* __restrict__ w2, const float* __restrict__ b2,
          const float* __restrict__ w3, const float* __restrict__ b3,
          const float* __restrict__ w4,
          const float* __restrict__ um) {
    extern __shared__ char smem[];
    const uint32_t smem_base = smem_to_u32(smem);
    const int tid = threadIdx.x;
    const int w = tid >> 5;          // warp id = pixel row it owns = halo channel it loads
    const int lane = tid & 31;
    float* sX   = reinterpret_cast<float*>(smem + OFF_X);    // [ch][324]
    float* sStg = reinterpret_cast<float*>(smem + OFF_STG);  // [ch][256]
    const float* sB1 = reinterpret_cast<float*>(smem + OFF_B1);
    const float* sB2 = reinterpret_cast<float*>(smem + OFF_B2);
    const float* sB3 = reinterpret_cast<float*>(smem + OFF_B3);

    // preload first tile's halo into registers (overlaps weight staging LDGs)
    float hreg[11];
    {
        const int t0 = blockIdx.x;
        const int b0r = t0 >> 8, r0 = t0 & 255;
        halo_ld(hreg, x + (size_t)b0r * CH * IMG * IMG + (size_t)w * IMG * IMG,
                (r0 & 15) * TILE, (r0 >> 4) * TILE, lane);
    }

    // one-time: stage weights + biases
    stage_w(w1, smem + OFF_W1, 128, 64, SB1, tid);
    stage_w(w2, smem + OFF_W2, 128, 128, SB2, tid);
    stage_w(w3, smem + OFF_W3, 128, 128, SB2, tid);
    stage_w(w4, smem + OFF_W4, 16, 128, SB2, tid);
    if (tid < HID) {
        reinterpret_cast<float*>(smem + OFF_B1)[tid] = b1[tid];
        reinterpret_cast<float*>(smem + OFF_B2)[tid] = b2[tid];
        reinterpret_cast<float*>(smem + OFF_B3)[tid] = b3[tid];
    }

    for (int t = blockIdx.x; t < TOTAL_TILES; t += gridDim.x) {
        const int b = t >> 8;
        const int r = t & 255;
        const int x0 = (r & 15) * TILE, y0 = (r >> 4) * TILE;

        // store prefetched halo regs -> sX (prior iter's sX readers finished
        // before its pre-writeout barrier; writeout touches only sStg)
        halo_st(hreg, sX + w * 324, lane);
        __syncthreads();   // full halo visible (conv needs ALL channels)

        // ---- per-warp conv of OWN pixel row y=w -> A1 rows 16w..16w+15 ----
        // (A1 rows written here are read ONLY by this warp's ldsm below)
        {
            const int px = lane & 15;
            const int c0 = (lane >> 4) << 3;   // 0 or 8
            char* arow = smem + OFF_A1 + (16 * w + px) * SB1;
#pragma unroll
            for (int ci = 0; ci < 8; ci++) {
                const int c = c0 + ci;
                const float* base = sX + c * 324 + w * 18 + px;
                float v00 = base[0],  v01 = base[1],  v02 = base[2];
                float v10 = base[18], v11 = base[19], v12 = base[20];
                float v20 = base[36], v21 = base[37], v22 = base[38];
                float idn = v11;
                float sx = (v02 + 2.0f * v12 + v22) - (v00 + 2.0f * v10 + v20);
                float sy = (v20 + 2.0f * v21 + v22) - (v00 + 2.0f * v01 + v02);
                float lap = v00 + v01 + v02 + v10 + v12 + v20 + v21 + v22 - 8.0f * v11;
                *reinterpret_cast<uint32_t*>(arow + c * 8)     = pack_bf16x2(idn, sx);
                *reinterpret_cast<uint32_t*>(arow + c * 8 + 4) = pack_bf16x2(sy, lap);
            }
        }
        // pre-alive for own row (lanes 0..15, 3x3 max ch0/1, -inf OOB via clip)
        if (lane < 16) {
            const int px = lane;
            float mx0 = -CUDART_INF_F, mx1 = -CUDART_INF_F;
#pragma unroll
            for (int dr = 0; dr < 3; dr++)
#pragma unroll
                for (int dc = 0; dc < 3; dc++) {
                    int gy = y0 + w + dr - 1, gx = x0 + px + dc - 1;
                    if (gy >= 0 && gy < IMG && gx >= 0 && gx < IMG) {
                        mx0 = fmaxf(mx0, sX[0 * 324 + (w + dr) * 18 + (px + dc)]);
                        mx1 = fmaxf(mx1, sX[1 * 324 + (w + dr) * 18 + (px + dc)]);
                    }
                }
            float s = fabsf(mx0) + fabsf(mx1);
            g_pre[b * (IMG * IMG) + (y0 + w) * IMG + (x0 + px)] = (s > 0.01f) ? 1 : 0;
        }

        // prefetch um (residual inputs) + next tile's halo: latency hidden by MLP
        const float uml = um[b * (IMG * IMG) + (y0 + w) * IMG + x0 + (lane >> 2)];
        const float umh = um[b * (IMG * IMG) + (y0 + w) * IMG + x0 + (lane >> 2) + 8];
        {
            const int tn = t + gridDim.x;
            if (tn < TOTAL_TILES) {
                const int bn = tn >> 8, rn = tn & 255;
                halo_ld(hreg, x + (size_t)bn * CH * IMG * IMG + (size_t)w * IMG * IMG,
                        (rn & 15) * TILE, (rn >> 4) * TILE, lane);
            }
        }

        __syncwarp();   // order own conv STS before own ldsm (same-warp visibility)

        // ---- per-warp register-resident MLP chain (rows m=16w..16w+15) ----
        {
            uint32_t a1[4][4];
            {
                const uint32_t abase = smem_base + OFF_A1
                    + (uint32_t)(16 * w + (lane & 15)) * SB1 + (uint32_t)(lane >> 4) * 16;
#pragma unroll
                for (int kc = 0; kc < 4; kc++)
                    ldsm4(a1[kc][0], a1[kc][1], a1[kc][2], a1[kc][3], abase + kc * 32);
            }
            float c[16][4];
#pragma unroll
            for (int j = 0; j < 16; j++) { c[j][0] = c[j][1] = c[j][2] = c[j][3] = 0.f; }
            gemm<4, 16>(a1, c, smem_base + OFF_W1, SB1, lane);

            uint32_t a2[8][4];
            transition<16>(c, a2, sB1, lane);
#pragma unroll
            for (int j = 0; j < 16; j++) { c[j][0] = c[j][1] = c[j][2] = c[j][3] = 0.f; }
            gemm<8, 16>(a2, c, smem_base + OFF_W2, SB2, lane);

            uint32_t a3[8][4];
            transition<16>(c, a3, sB2, lane);
#pragma unroll
            for (int j = 0; j < 16; j++) { c[j][0] = c[j][1] = c[j][2] = c[j][3] = 0.f; }
            gemm<8, 16>(a3, c, smem_base + OFF_W3, SB2, lane);

            uint32_t a4[8][4];
            transition<16>(c, a4, sB3, lane);
            float c4[2][4];
#pragma unroll
            for (int j = 0; j < 2; j++) { c4[j][0] = c4[j][1] = c4[j][2] = c4[j][3] = 0.f; }
            gemm<8, 2>(a4, c4, smem_base + OFF_W4, SB2, lane);

            // residual update -> staging (x fp32 from halo, dy bf16-derived)
            const int pxl = lane >> 2, pxh = pxl + 8;
            const int ch0 = 2 * (lane & 3);
#pragma unroll
            for (int j = 0; j < 2; j++) {
                const int cA = 8 * j + ch0, cB = cA + 1;
                const float xAl = sX[cA * 324 + (w + 1) * 18 + (pxl + 1)];
                const float xBl = sX[cB * 324 + (w + 1) * 18 + (pxl + 1)];
                const float xAh = sX[cA * 324 + (w + 1) * 18 + (pxh + 1)];
                const float xBh = sX[cB * 324 + (w + 1) * 18 + (pxh + 1)];
                sStg[cA * 256 + w * 16 + pxl] = xAl + c4[j][0] * uml;
                sStg[cB * 256 + w * 16 + pxl] = xBl + c4[j][1] * uml;
                sStg[cA * 256 + w * 16 + pxh] = xAh + c4[j][2] * umh;
                sStg[cB * 256 + w * 16 + pxh] = xBh + c4[j][3] * umh;
            }
        }
        __syncthreads();

        // coalesced write-out: thread -> (ch, y, half-row of 8 px)
        {
            const int ch = tid >> 5, rest = tid & 31;
            const int yy = rest >> 1, half = rest & 1;
            const float* src = sStg + ch * 256 + yy * 16 + half * 8;
            float* dst = g_xnew + (size_t)b * CH * IMG * IMG
                       + (size_t)ch * IMG * IMG + (size_t)(y0 + yy) * IMG + x0 + half * 8;
            float4 v0 = *reinterpret_cast<const float4*>(src);
            float4 v1 = *reinterpret_cast<const float4*>(src + 4);
            *reinterpret_cast<float4*>(dst)     = v0;
            *reinterpret_cast<float4*>(dst + 4) = v1;
        }
    }
}

// =============================== pass 2 ====================================
// tile 64x8, 128 threads, 4 px/thread via float4
__global__ void __launch_bounds__(128, 8)
nca_pass2(float* __restrict__ out) {
    __shared__ float s0[10][68];
    __shared__ float s1[10][68];
    const int tid = threadIdx.x;
    const int bx = blockIdx.x, by = blockIdx.y, b = blockIdx.z;
    const int x0 = bx * 64, y0 = by * 8;
    const float* xb = g_xnew + (size_t)b * CH * IMG * IMG;

    for (int i = tid; i < 10 * 66; i += 128) {
        int r = i / 66, col = i % 66;
        int gy = y0 + r - 1, gx = x0 + col - 1;
        float v0 = -CUDART_INF_F, v1 = -CUDART_INF_F;
        if (gy >= 0 && gy < IMG && gx >= 0 && gx < IMG) {
            v0 = xb[gy * IMG + gx];
            v1 = xb[IMG * IMG + gy * IMG + gx];
        }
        s0[r][col] = v0;
        s1[r][col] = v1;
    }
    __syncthreads();

    const int tx = tid & 15, ty = tid >> 4;   // ty 0..7
    const int px0 = tx * 4;
    const int gy = y0 + ty;

    float alive[4];
#pragma unroll
    for (int j = 0; j < 4; j++) {
        float mx0 = -CUDART_INF_F, mx1 = -CUDART_INF_F;
#pragma unroll
        for (int dr = 0; dr < 3; dr++)
#pragma unroll
            for (int dc = 0; dc < 3; dc++) {
                mx0 = fmaxf(mx0, s0[ty + dr][px0 + j + dc]);
                mx1 = fmaxf(mx1, s1[ty + dr][px0 + j + dc]);
            }
        alive[j] = (fabsf(mx0) + fabsf(mx1) > 0.01f) ? 1.0f : 0.0f;
    }
    // combine with pre-alive (4 consecutive bytes, 4-aligned)
    {
        uchar4 pre = *reinterpret_cast<const uchar4*>(
            g_pre + b * (IMG * IMG) + gy * IMG + x0 + px0);
        alive[0] *= (float)pre.x;
        alive[1] *= (float)pre.y;
        alive[2] *= (float)pre.z;
        alive[3] *= (float)pre.w;
    }

    const size_t base = (size_t)b * CH * IMG * IMG + (size_t)gy * IMG + x0 + px0;
#pragma unroll
    for (int c = 0; c < CH; c++) {
        float4 v = *reinterpret_cast<const float4*>(g_xnew + base + (size_t)c * IMG * IMG);
        v.x *= alive[0]; v.y *= alive[1]; v.z *= alive[2]; v.w *= alive[3];
        *reinterpret_cast<float4*>(out + base + (size_t)c * IMG * IMG) = v;
    }
}

extern "C" void kernel_launch(void* const* d_in, const int* in_sizes, int n_in,
                              void* d_out, int out_size) {
    const float* x  = (const float*)d_in[0];
    const float* w1 = (const float*)d_in[1];
    const float* b1 = (const float*)d_in[2];
    const float* w2 = (const float*)d_in[3];
    const float* b2 = (const float*)d_in[4];
    const float* w3 = (const float*)d_in[5];
    const float* b3 = (const float*)d_in[6];
    const float* w4 = (const float*)d_in[7];
    const float* um = (const float*)d_in[8];

    cudaFuncSetAttribute(nca_pass1, cudaFuncAttributeMaxDynamicSharedMemorySize,
                         SMEM_BYTES);
    nca_pass1<<<148, 512, SMEM_BYTES>>>(x, w1, b1, w2, b2, w3, b3, w4, um);

    dim3 g2(IMG / 64, IMG / 8, 32);
    nca_pass2<<<g2, 128>>>((float*)d_out);
}